// round 8
// baseline (speedup 1.0000x reference)
#include <cuda_runtime.h>
#include <math.h>

// Problem constants
#define B 256
#define N 256
#define D 512
#define EPSV 1e-8f

#define DSPLIT 16
#define DCHUNK (D / DSPLIT)   // 32 d's per block
#define DC4 (DCHUNK / 4)      // 8 float4 columns per block
#define NGROUPS 16
#define NCHUNK (N / NGROUPS)  // 16 n-rows per thread (MLP=16, the R6 winner)
#define TPB (DC4 * NGROUPS)   // 128 threads per block

#define D4 (D / 4)               // 128
#define PB4 ((N + D) * D4)       // new_pd float4 stride per batch = 98304
#define DIAG4 (N * D4)           // diag region offset within batch = 32768

// Register-cached mega-kernel, small-block variant: keeps R6's per-thread
// depth (16 float4 cached in registers, 16-deep load batches) but uses
// 128-thread blocks at 5 blocks/SM, so when one block stalls at its
// __syncthreads reduction, four independent blocks keep the memory system
// streaming.
//  Pass 1: load slice into registers (abs-sum) + interleaved diag zero-fill.
//  Reduce: lam/beta/delta; write new_central/new_err; patch 32 diag scalars.
//  Pass 2: scale register-resident values, store scaled_pd.
//  pd read from DRAM exactly once.
__global__ __launch_bounds__(TPB, 5) void k_mega(const float* __restrict__ cv,
                                                 const float4* __restrict__ pd4,
                                                 const float* __restrict__ err,
                                                 float* __restrict__ out_central,
                                                 float4* __restrict__ out_pd4,
                                                 float* __restrict__ out_err) {
    const int b = blockIdx.x;
    const int h = blockIdx.y;        // d-chunk index, 0..15
    const int tid = threadIdx.x;
    const int d4 = tid & (DC4 - 1);  // 0..7  (float4 column within chunk)
    const int g = tid >> 3;          // 0..15 (n-group)

    __shared__ float4 s_acc[NGROUPS][DC4];
    __shared__ float4 s_lam[DC4];

    // Base pointer for this thread's float4 column of the pd slice
    const float4* p = pd4 + (size_t)b * N * D4 + (size_t)(g * NCHUNK) * D4
                      + h * DC4 + d4;

    // Diag share of this block: rows [h*32, h*32+32) of batch b
    // = 32 rows * 128 float4 = 4096 float4; zero-filled 256 float4/iter.
    float4* diag_blk = out_pd4 + (size_t)b * PB4 + DIAG4 + (size_t)h * DCHUNK * D4;
    const float4 z = make_float4(0.f, 0.f, 0.f, 0.f);

    // Pass 1: load slice into registers + abs-sum + diag zero-fill interleave
    float4 v[NCHUNK];
    float4 acc = make_float4(0.f, 0.f, 0.f, 0.f);
#pragma unroll
    for (int n = 0; n < NCHUNK; n++) {
        v[n] = p[(size_t)n * D4];
        diag_blk[n * 256 + tid] = z;
        diag_blk[n * 256 + 128 + tid] = z;
        acc.x += fabsf(v[n].x);
        acc.y += fabsf(v[n].y);
        acc.z += fabsf(v[n].z);
        acc.w += fabsf(v[n].w);
    }
    s_acc[g][d4] = acc;
    __syncthreads();

    // Combine groups + compute lam/beta/delta: threads 0..31, one d each
    if (tid < DCHUNK) {
        const int dc4 = tid >> 2;
        const int lane = tid & 3;
        float r = 0.f;
#pragma unroll
        for (int gg = 0; gg < NGROUPS; gg++)
            r += ((const float*)&s_acc[gg][dc4])[lane];

        const int dg = h * DCHUNK + tid;  // global d index
        const int bd = b * D + dg;
        const float e = err[bd];
        const float c = cv[bd];

        const float radius = r + fabsf(e);
        const float lower = c - radius;
        const float upper = c + radius;
        const float rl = fmaxf(lower, 0.f);
        const float ru = fmaxf(upper, 0.f);

        float lam = (ru - rl) / (upper - lower + EPSV);
        if (lower >= 0.f) lam = 1.f;
        if (upper < 0.f) lam = 0.f;
        if (isnan(lam)) lam = 0.f;
        lam = fminf(fmaxf(lam, 0.f), 1.f);

        const float beta = (rl - lam * lower) * 0.5f;
        const float delta = fabsf(beta);

        out_central[bd] = lam * c + beta;
        out_err[bd] = lam * e;

        // Patch diagonal: local diag row tid has its element at global col dg.
        // Ordered after the zero-fill by the __syncthreads above.
        ((float*)diag_blk)[(size_t)tid * D + dg] = delta;

        ((float*)&s_lam[dc4])[lane] = lam;
    }
    __syncthreads();

    // Pass 2: scale register-resident values and store scaled_pd.
    // new_pd layout: (B, N+D, D); rows [0, N) are scaled_pd.
    const float4 lam4 = s_lam[d4];
    float4* o = out_pd4 + (size_t)b * PB4 + (size_t)(g * NCHUNK) * D4
                + h * DC4 + d4;
#pragma unroll
    for (int n = 0; n < NCHUNK; n++) {
        float4 w;
        w.x = v[n].x * lam4.x;
        w.y = v[n].y * lam4.y;
        w.z = v[n].z * lam4.z;
        w.w = v[n].w * lam4.w;
        o[(size_t)n * D4] = w;
    }
}

extern "C" void kernel_launch(void* const* d_in, const int* in_sizes, int n_in,
                              void* d_out, int out_size) {
    const float* cv = (const float*)d_in[0];   // (256, 512)
    const float* pd = (const float*)d_in[1];   // (256, 256, 512)
    const float* err = (const float*)d_in[2];  // (256, 512)

    float* out = (float*)d_out;
    // Output layout: [new_central (B*D)] [new_pd (B*(N+D)*D)] [new_err (B*D)]
    float* out_central = out;
    float* out_pd = out + (size_t)B * D;
    float* out_err = out + (size_t)B * D + (size_t)B * (N + D) * D;

    dim3 grid(B, DSPLIT);  // 4096 blocks of 128 threads
    k_mega<<<grid, TPB>>>(cv, (const float4*)pd, err,
                          out_central, (float4*)out_pd, out_err);
}

// round 9
// speedup vs baseline: 1.0416x; 1.0416x over previous
#include <cuda_runtime.h>
#include <math.h>

// Problem constants
#define B 256
#define N 256
#define D 512
#define EPSV 1e-8f

// R6 geometry (the proven winner): DSPLIT=8, 64-d chunks, 256 threads,
// 2 blocks/SM, 16 float4 register cache per thread (MLP=16).
#define DSPLIT 8
#define DCHUNK (D / DSPLIT)   // 64 d's per block
#define DC4 (DCHUNK / 4)      // 16 float4 columns per block
#define NGROUPS 16
#define NCHUNK (N / NGROUPS)  // 16 n-rows per thread
// block = DC4 * NGROUPS = 256 threads

#define D4 (D / 4)               // 128
#define PB4 ((N + D) * D4)       // new_pd float4 stride per batch = 98304
#define DIAG4 (N * D4)           // diag region offset within batch = 32768

// Register-cached mega-kernel, single-barrier variant.
//  Pass 1: load slice into registers (abs-sum) + interleaved diag zero-fill.
//  Barrier (the only one).
//  Every thread redundantly computes lam4 for its own d4 column from s_acc
//  (cheap: issue pipe is ~4.5% busy), so no second barrier / no s_lam
//  broadcast is needed; g==0 threads additionally write new_central/new_err
//  and patch the diagonal scalars.
//  Pass 2: scale register-resident values, store scaled_pd.
//  pd is read from DRAM exactly once.
__global__ __launch_bounds__(256, 2) void k_mega(const float* __restrict__ cv,
                                                 const float4* __restrict__ pd4,
                                                 const float* __restrict__ err,
                                                 float* __restrict__ out_central,
                                                 float4* __restrict__ out_pd4,
                                                 float* __restrict__ out_err) {
    const int b = blockIdx.x;
    const int h = blockIdx.y;        // d-chunk index, 0..7
    const int tid = threadIdx.x;
    const int d4 = tid & (DC4 - 1);  // 0..15 (float4 column within chunk)
    const int g = tid >> 4;          // 0..15 (n-group)

    __shared__ float4 s_acc[NGROUPS][DC4];

    // Base pointer for this thread's float4 column of the pd slice
    const float4* p = pd4 + (size_t)b * N * D4 + (size_t)(g * NCHUNK) * D4
                      + h * DC4 + d4;

    // Diag share of this block: rows [h*64, h*64+64) of batch b
    // = 64 rows * 128 float4 = 8192 float4; zero-filled 512 float4/iter.
    float4* diag_blk = out_pd4 + (size_t)b * PB4 + DIAG4 + (size_t)h * DCHUNK * D4;
    const float4 z = make_float4(0.f, 0.f, 0.f, 0.f);

    // Pass 1: load slice into registers + abs-sum + diag zero-fill interleave
    float4 v[NCHUNK];
    float4 acc = make_float4(0.f, 0.f, 0.f, 0.f);
#pragma unroll
    for (int n = 0; n < NCHUNK; n++) {
        v[n] = p[(size_t)n * D4];
        diag_blk[n * 512 + tid] = z;
        diag_blk[n * 512 + 256 + tid] = z;
        acc.x += fabsf(v[n].x);
        acc.y += fabsf(v[n].y);
        acc.z += fabsf(v[n].z);
        acc.w += fabsf(v[n].w);
    }
    s_acc[g][d4] = acc;
    __syncthreads();  // the ONLY barrier

    // Every thread computes lam for the 4 d's of its own column d4.
    // Redundant across the 16 threads sharing d4 — but removes the second
    // barrier. g==0 threads also emit the per-d scalar outputs.
    float4 lam4;
#pragma unroll
    for (int ll = 0; ll < 4; ll++) {
        float r = 0.f;
#pragma unroll
        for (int gg = 0; gg < NGROUPS; gg++)
            r += ((const float*)&s_acc[gg][d4])[ll];

        const int dl = d4 * 4 + ll;       // d within chunk, 0..63
        const int dg = h * DCHUNK + dl;   // global d index
        const int bd = b * D + dg;
        const float e = err[bd];          // L1 broadcast across the 16 readers
        const float c = cv[bd];

        const float radius = r + fabsf(e);
        const float lower = c - radius;
        const float upper = c + radius;
        const float rl = fmaxf(lower, 0.f);
        const float ru = fmaxf(upper, 0.f);

        float lam = (ru - rl) / (upper - lower + EPSV);
        if (lower >= 0.f) lam = 1.f;
        if (upper < 0.f) lam = 0.f;
        if (isnan(lam)) lam = 0.f;
        lam = fminf(fmaxf(lam, 0.f), 1.f);

        ((float*)&lam4)[ll] = lam;

        if (g == 0) {
            const float beta = (rl - lam * lower) * 0.5f;
            const float delta = fabsf(beta);
            out_central[bd] = lam * c + beta;
            out_err[bd] = lam * e;
            // Patch diagonal: local diag row dl has its element at global
            // col dg. Zero-fill of this address happened before the barrier.
            ((float*)diag_blk)[(size_t)dl * D + dg] = delta;
        }
    }

    // Pass 2: scale register-resident values and store scaled_pd.
    // new_pd layout: (B, N+D, D); rows [0, N) are scaled_pd.
    float4* o = out_pd4 + (size_t)b * PB4 + (size_t)(g * NCHUNK) * D4
                + h * DC4 + d4;
#pragma unroll
    for (int n = 0; n < NCHUNK; n++) {
        float4 w;
        w.x = v[n].x * lam4.x;
        w.y = v[n].y * lam4.y;
        w.z = v[n].z * lam4.z;
        w.w = v[n].w * lam4.w;
        o[(size_t)n * D4] = w;
    }
}

extern "C" void kernel_launch(void* const* d_in, const int* in_sizes, int n_in,
                              void* d_out, int out_size) {
    const float* cv = (const float*)d_in[0];   // (256, 512)
    const float* pd = (const float*)d_in[1];   // (256, 256, 512)
    const float* err = (const float*)d_in[2];  // (256, 512)

    float* out = (float*)d_out;
    // Output layout: [new_central (B*D)] [new_pd (B*(N+D)*D)] [new_err (B*D)]
    float* out_central = out;
    float* out_pd = out + (size_t)B * D;
    float* out_err = out + (size_t)B * D + (size_t)B * (N + D) * D;

    dim3 grid(B, DSPLIT);  // 2048 blocks of 256 threads
    k_mega<<<grid, 256>>>(cv, (const float4*)pd, err,
                          out_central, (float4*)out_pd, out_err);
}